// round 3
// baseline (speedup 1.0000x reference)
#include <cuda_runtime.h>
#include <stdint.h>

#define NVIS 4096
#define NHID 1024
#define TT   64
#define BB   32

#define VM_OFF 0
#define RM_OFF (NVIS*TT*BB)              /* 8388608  */
#define RT_OFF (RM_OFF + NHID*TT*BB)     /* 10485760 */

// ---------------------------------------------------------------------------
// Scratch (static device globals — no allocation). ~1.3 MB total.
// ---------------------------------------------------------------------------
__device__ __align__(16) float g_vm[NVIS * BB];    // vm      [NV][B]
__device__ __align__(16) float g_r[NHID * BB];     // r_prev  [NH][B]
__device__ __align__(16) float g_hT[BB * NHID];    // h       [B][NH]
__device__ __align__(16) float g_bias[NHID * BB];  // cached hid bias [NH][B]

// ---------------------------------------------------------------------------
// Threefry-2x32 (exact: 20 rounds, 5 key injections)
// ---------------------------------------------------------------------------
__host__ __device__ __forceinline__ void tf2x32(uint32_t k0, uint32_t k1,
                                                uint32_t x0, uint32_t x1,
                                                uint32_t& o0, uint32_t& o1) {
    uint32_t ks2 = k0 ^ k1 ^ 0x1BD11BDAu;
    x0 += k0; x1 += k1;
#define TF_R(r) { x0 += x1; x1 = (x1 << (r)) | (x1 >> (32 - (r))); x1 ^= x0; }
    TF_R(13) TF_R(15) TF_R(26) TF_R(6)   x0 += k1;  x1 += ks2 + 1u;
    TF_R(17) TF_R(29) TF_R(16) TF_R(24)  x0 += ks2; x1 += k0  + 2u;
    TF_R(13) TF_R(15) TF_R(26) TF_R(6)   x0 += k0;  x1 += k1  + 3u;
    TF_R(17) TF_R(29) TF_R(16) TF_R(24)  x0 += k1;  x1 += ks2 + 4u;
    TF_R(13) TF_R(15) TF_R(26) TF_R(6)   x0 += ks2; x1 += k0  + 5u;
#undef TF_R
    o0 = x0; o1 = x1;
}

// Partitionable threefry random bits (JAX >= 0.4.36 default):
// element i: counter = (hi=0, lo=i), bits = o0 ^ o1,
// u = bitcast((bits>>9)|0x3f800000) - 1.0f
__device__ __forceinline__ float jax_uniform(uint32_t k0, uint32_t k1, uint32_t idx) {
    uint32_t o0, o1;
    tf2x32(k0, k1, 0u, idx, o0, o1);
    uint32_t bits = o0 ^ o1;
    return __uint_as_float((bits >> 9) | 0x3f800000u) - 1.0f;
}

__device__ __forceinline__ float sigmoidf_(float x) {
    return 1.0f / (1.0f + expf(-x));
}

// ---------------------------------------------------------------------------
// Hidden kernel: 2 h-rows per thread, strict sequential-k chain per output.
// grid 256, block 64 (2 warps). Warp = 32 b-lanes, owns h rows {2g, 2g+1}.
// phase 0: t=0 hid1  (bias = b_init[h]; cache bias; write rt, g_r, g_hT)
// phase 1: t>0 hid1  (bias = seq(U@r) + b_h[h]; cache; write rt, g_r, g_hT)
// phase 2: hid2      (bias = cached; write r_model sample + g_hT)
// ---------------------------------------------------------------------------
__global__ void __launch_bounds__(64) hid_kernel(
    const float* __restrict__ W,
    const float* __restrict__ vsrc, int vstride,
    const float* __restrict__ U,
    const float* __restrict__ bvec,
    int phase,
    float* __restrict__ r_out,   // rt column     (phase 0/1)
    float* __restrict__ s_out,   // r_model column(phase 2)
    uint32_t kk0, uint32_t kk1)
{
    const int gw   = blockIdx.x * 2 + (threadIdx.x >> 5);   // 0..511
    const int b    = threadIdx.x & 31;
    const int h0   = gw * 2;
    const int h1   = h0 + 1;

    float bias0, bias1;
    if (phase == 1) {
        float au0 = 0.f, au1 = 0.f;
        const float4* U0 = reinterpret_cast<const float4*>(U + (size_t)h0 * NHID);
        const float4* U1 = reinterpret_cast<const float4*>(U + (size_t)h1 * NHID);
        const float*  rp = g_r + b;
#pragma unroll 4
        for (int kq = 0; kq < NHID / 4; kq++) {
            float4 u0 = U0[kq], u1 = U1[kq];
            float r0 = rp[(4 * kq + 0) * 32];
            float r1 = rp[(4 * kq + 1) * 32];
            float r2 = rp[(4 * kq + 2) * 32];
            float r3 = rp[(4 * kq + 3) * 32];
            au0 = fmaf(u0.x, r0, au0); au1 = fmaf(u1.x, r0, au1);
            au0 = fmaf(u0.y, r1, au0); au1 = fmaf(u1.y, r1, au1);
            au0 = fmaf(u0.z, r2, au0); au1 = fmaf(u1.z, r2, au1);
            au0 = fmaf(u0.w, r3, au0); au1 = fmaf(u1.w, r3, au1);
        }
        bias0 = au0 + bvec[h0];
        bias1 = au1 + bvec[h1];
        g_bias[h0 * 32 + b] = bias0;
        g_bias[h1 * 32 + b] = bias1;
    } else if (phase == 0) {
        bias0 = bvec[h0];
        bias1 = bvec[h1];
        g_bias[h0 * 32 + b] = bias0;
        g_bias[h1 * 32 + b] = bias1;
    } else {
        bias0 = g_bias[h0 * 32 + b];
        bias1 = g_bias[h1 * 32 + b];
    }

    float aw0 = 0.f, aw1 = 0.f;
    const float4* W0 = reinterpret_cast<const float4*>(W + (size_t)h0 * NVIS);
    const float4* W1 = reinterpret_cast<const float4*>(W + (size_t)h1 * NVIS);
    const float*  vp = vsrc + b;
#pragma unroll 4
    for (int kq = 0; kq < NVIS / 4; kq++) {
        float4 w0 = W0[kq], w1 = W1[kq];
        float v0 = __ldg(vp + (size_t)(4 * kq + 0) * vstride);
        float v1 = __ldg(vp + (size_t)(4 * kq + 1) * vstride);
        float v2 = __ldg(vp + (size_t)(4 * kq + 2) * vstride);
        float v3 = __ldg(vp + (size_t)(4 * kq + 3) * vstride);
        aw0 = fmaf(w0.x, v0, aw0); aw1 = fmaf(w1.x, v0, aw1);
        aw0 = fmaf(w0.y, v1, aw0); aw1 = fmaf(w1.y, v1, aw1);
        aw0 = fmaf(w0.z, v2, aw0); aw1 = fmaf(w1.z, v2, aw1);
        aw0 = fmaf(w0.w, v3, aw0); aw1 = fmaf(w1.w, v3, aw1);
    }
    float r0 = sigmoidf_(aw0 + bias0);
    float r1 = sigmoidf_(aw1 + bias1);

    if (phase != 2) {
        r_out[h0 * (TT * BB) + b] = r0;
        r_out[h1 * (TT * BB) + b] = r1;
        g_r[h0 * 32 + b] = r0;
        g_r[h1 * 32 + b] = r1;
    }
    float u0 = jax_uniform(kk0, kk1, (uint32_t)(h0 * BB + b));
    float u1 = jax_uniform(kk0, kk1, (uint32_t)(h1 * BB + b));
    float s0 = (u0 < r0) ? 1.0f : 0.0f;
    float s1 = (u1 < r1) ? 1.0f : 0.0f;
    g_hT[b * NHID + h0] = s0;
    g_hT[b * NHID + h1] = s1;
    if (phase == 2) {
        s_out[h0 * (TT * BB) + b] = s0;
        s_out[h1 * (TT * BB) + b] = s1;
    }
}

// ---------------------------------------------------------------------------
// Visible kernel: out[i][b] = bern(sigmoid(seq_j W[j][i]*h[j][b] + b_v[i]))
// 4 i x 2 b per thread; strict sequential-j chain per output.
// grid (32, 8), block 64 (2 warps). Warp = b-pair; lane -> i0 = 4*lane.
// mode 0: write vm -> g_vm [NV][B] ; mode 1: write v_model column -> outp
// ---------------------------------------------------------------------------
__global__ void __launch_bounds__(64) vis_kernel(
    const float* __restrict__ W,
    const float* __restrict__ bv,
    int mode,
    float* __restrict__ outp,
    uint32_t kk0, uint32_t kk1)
{
    const int lane = threadIdx.x & 31;
    const int bp   = blockIdx.y * 2 + (threadIdx.x >> 5);  // 0..15
    const int b0   = bp * 2, b1 = b0 + 1;
    const int i0   = blockIdx.x * 128 + lane * 4;

    float a0[4] = {0.f, 0.f, 0.f, 0.f};
    float a1[4] = {0.f, 0.f, 0.f, 0.f};
    const float4* hA = reinterpret_cast<const float4*>(g_hT + (size_t)b0 * NHID);
    const float4* hB = reinterpret_cast<const float4*>(g_hT + (size_t)b1 * NHID);
    const float4* Wp = reinterpret_cast<const float4*>(W + i0);

#pragma unroll 2
    for (int j4 = 0; j4 < NHID / 4; j4++) {
        float4 ha = hA[j4];
        float4 hb = hB[j4];
        float4 w4;
        w4 = Wp[(size_t)(4 * j4 + 0) * (NVIS / 4)];
        a0[0] = fmaf(w4.x, ha.x, a0[0]); a0[1] = fmaf(w4.y, ha.x, a0[1]);
        a0[2] = fmaf(w4.z, ha.x, a0[2]); a0[3] = fmaf(w4.w, ha.x, a0[3]);
        a1[0] = fmaf(w4.x, hb.x, a1[0]); a1[1] = fmaf(w4.y, hb.x, a1[1]);
        a1[2] = fmaf(w4.z, hb.x, a1[2]); a1[3] = fmaf(w4.w, hb.x, a1[3]);
        w4 = Wp[(size_t)(4 * j4 + 1) * (NVIS / 4)];
        a0[0] = fmaf(w4.x, ha.y, a0[0]); a0[1] = fmaf(w4.y, ha.y, a0[1]);
        a0[2] = fmaf(w4.z, ha.y, a0[2]); a0[3] = fmaf(w4.w, ha.y, a0[3]);
        a1[0] = fmaf(w4.x, hb.y, a1[0]); a1[1] = fmaf(w4.y, hb.y, a1[1]);
        a1[2] = fmaf(w4.z, hb.y, a1[2]); a1[3] = fmaf(w4.w, hb.y, a1[3]);
        w4 = Wp[(size_t)(4 * j4 + 2) * (NVIS / 4)];
        a0[0] = fmaf(w4.x, ha.z, a0[0]); a0[1] = fmaf(w4.y, ha.z, a0[1]);
        a0[2] = fmaf(w4.z, ha.z, a0[2]); a0[3] = fmaf(w4.w, ha.z, a0[3]);
        a1[0] = fmaf(w4.x, hb.z, a1[0]); a1[1] = fmaf(w4.y, hb.z, a1[1]);
        a1[2] = fmaf(w4.z, hb.z, a1[2]); a1[3] = fmaf(w4.w, hb.z, a1[3]);
        w4 = Wp[(size_t)(4 * j4 + 3) * (NVIS / 4)];
        a0[0] = fmaf(w4.x, ha.w, a0[0]); a0[1] = fmaf(w4.y, ha.w, a0[1]);
        a0[2] = fmaf(w4.z, ha.w, a0[2]); a0[3] = fmaf(w4.w, ha.w, a0[3]);
        a1[0] = fmaf(w4.x, hb.w, a1[0]); a1[1] = fmaf(w4.y, hb.w, a1[1]);
        a1[2] = fmaf(w4.z, hb.w, a1[2]); a1[3] = fmaf(w4.w, hb.w, a1[3]);
    }

#pragma unroll
    for (int q = 0; q < 4; q++) {
        float bias = bv[i0 + q];
        float r0 = sigmoidf_(a0[q] + bias);
        float r1 = sigmoidf_(a1[q] + bias);
        float u0 = jax_uniform(kk0, kk1, (uint32_t)((i0 + q) * BB + b0));
        float u1 = jax_uniform(kk0, kk1, (uint32_t)((i0 + q) * BB + b1));
        float s0 = (u0 < r0) ? 1.0f : 0.0f;
        float s1 = (u1 < r1) ? 1.0f : 0.0f;
        if (mode == 0) {
            g_vm[(size_t)(i0 + q) * BB + b0] = s0;
            g_vm[(size_t)(i0 + q) * BB + b1] = s1;
        } else {
            outp[(size_t)(i0 + q) * (TT * BB) + b0] = s0;
            outp[(size_t)(i0 + q) * (TT * BB) + b1] = s1;
        }
    }
}

// ---------------------------------------------------------------------------
// Host: partitionable-threefry key schedule + launch sequence
// ---------------------------------------------------------------------------
extern "C" void kernel_launch(void* const* d_in, const int* in_sizes, int n_in,
                              void* d_out, int out_size)
{
    const float* v      = (const float*)d_in[0];   // [NV, T, B]
    const float* W      = (const float*)d_in[1];   // [NH, NV]
    const float* U      = (const float*)d_in[2];   // [NH, NH]
    const float* b_v    = (const float*)d_in[3];
    const float* b_h    = (const float*)d_in[4];
    const float* b_init = (const float*)d_in[5];
    float* out = (float*)d_out;

    // master key(42) = (0, 42)
    // partitionable split(key, n): key_i = tf(key, 0, i) (both output words)
    uint32_t k0a, k0b, ksa, ksb;
    tf2x32(0u, 42u, 0u, 0u, k0a, k0b);   // k0 (t=0 step key)
    tf2x32(0u, 42u, 0u, 1u, ksa, ksb);   // ks
    static uint32_t sub[TT][4][2];
    for (int t = 0; t < TT; t++) {
        uint32_t sk0, sk1;
        if (t == 0) { sk0 = k0a; sk1 = k0b; }
        else         tf2x32(ksa, ksb, 0u, (uint32_t)(t - 1), sk0, sk1);
        for (int i = 0; i < 4; i++)
            tf2x32(sk0, sk1, 0u, (uint32_t)i, sub[t][i][0], sub[t][i][1]);
    }

    void* p;
    cudaGetSymbolAddress(&p, g_vm);
    const float* pvm = (const float*)p;

    for (int t = 0; t < TT; t++) {
        const float* vt = v + (size_t)t * BB;
        int ph1 = (t == 0) ? 0 : 1;
        // hid1: bias = (t==0 ? b_init : U@r + b_h); logit = W@v_t + bias
        hid_kernel<<<256, 64>>>(W, vt, TT * BB, U, (t == 0) ? b_init : b_h, ph1,
                                out + RT_OFF + (size_t)t * BB, nullptr,
                                sub[t][0][0], sub[t][0][1]);
        // vis1: vm = bern(sigmoid(W.T h + b_v)) -> g_vm
        vis_kernel<<<dim3(32, 8), 64>>>(W, b_v, 0, nullptr,
                                        sub[t][1][0], sub[t][1][1]);
        // hid2: logit = W@vm + cached bias -> r_model sample
        hid_kernel<<<256, 64>>>(W, pvm, BB, nullptr, nullptr, 2,
                                nullptr, out + RM_OFF + (size_t)t * BB,
                                sub[t][2][0], sub[t][2][1]);
        // vis2: v_model = bern(sigmoid(W.T h + b_v)) -> output
        vis_kernel<<<dim3(32, 8), 64>>>(W, b_v, 1, out + (size_t)t * BB,
                                        sub[t][3][0], sub[t][3][1]);
    }
}

// round 4
// speedup vs baseline: 1.2689x; 1.2689x over previous
#include <cuda_runtime.h>
#include <stdint.h>

#define NVIS 4096
#define NHID 1024
#define TT   64
#define BB   32

#define RM_OFF (NVIS*TT*BB)              /* 8388608  */
#define RT_OFF (RM_OFF + NHID*TT*BB)     /* 10485760 */

typedef unsigned long long ull;

// ---------------------------------------------------------------------------
// Scratch (static device globals — no allocation)
// Pair-packed layouts: X[k2][bp] (float4) = {x[2k2][b0], x[2k2][b1],
//                                            x[2k2+1][b0], x[2k2+1][b1]},  b0=2bp
// ---------------------------------------------------------------------------
__device__ __align__(16) float4 g_vP [TT * 2048 * 16];  // packed v, all t (33.5 MB)
__device__ __align__(16) float4 g_vmP[2048 * 16];       // packed vm
__device__ __align__(16) float4 g_rP [512 * 16];        // packed r_prev (k-dim = h)
__device__ __align__(16) float  g_hP [NHID * BB];       // h samples [j][b]
__device__ __align__(16) float  g_bias[NHID * BB];      // cached hid bias [h][b]

// ---------------------------------------------------------------------------
// Threefry-2x32 (exact; 20 rounds, 5 key injections) — DO NOT MODIFY (passing)
// ---------------------------------------------------------------------------
__host__ __device__ __forceinline__ void tf2x32(uint32_t k0, uint32_t k1,
                                                uint32_t x0, uint32_t x1,
                                                uint32_t& o0, uint32_t& o1) {
    uint32_t ks2 = k0 ^ k1 ^ 0x1BD11BDAu;
    x0 += k0; x1 += k1;
#define TF_R(r) { x0 += x1; x1 = (x1 << (r)) | (x1 >> (32 - (r))); x1 ^= x0; }
    TF_R(13) TF_R(15) TF_R(26) TF_R(6)   x0 += k1;  x1 += ks2 + 1u;
    TF_R(17) TF_R(29) TF_R(16) TF_R(24)  x0 += ks2; x1 += k0  + 2u;
    TF_R(13) TF_R(15) TF_R(26) TF_R(6)   x0 += k0;  x1 += k1  + 3u;
    TF_R(17) TF_R(29) TF_R(16) TF_R(24)  x0 += k1;  x1 += ks2 + 4u;
    TF_R(13) TF_R(15) TF_R(26) TF_R(6)   x0 += ks2; x1 += k0  + 5u;
#undef TF_R
    o0 = x0; o1 = x1;
}

__device__ __forceinline__ float jax_uniform(uint32_t k0, uint32_t k1, uint32_t idx) {
    uint32_t o0, o1;
    tf2x32(k0, k1, 0u, idx, o0, o1);
    uint32_t bits = o0 ^ o1;
    return __uint_as_float((bits >> 9) | 0x3f800000u) - 1.0f;
}

__device__ __forceinline__ float sigmoidf_(float x) {
    return 1.0f / (1.0f + expf(-x));
}

// ---------------------------------------------------------------------------
// f32x2 packed helpers (per-lane IEEE identical to scalar fmaf sequence)
// ---------------------------------------------------------------------------
__device__ __forceinline__ ull dup2(float x) {
    ull r; asm("mov.b64 %0, {%1, %1};" : "=l"(r) : "f"(x)); return r;
}
__device__ __forceinline__ ull ffma2(ull a, ull b, ull c) {
    ull d; asm("fma.rn.f32x2 %0, %1, %2, %3;" : "=l"(d) : "l"(a), "l"(b), "l"(c));
    return d;
}
__device__ __forceinline__ ull fadd2(ull a, ull b) {
    ull d; asm("add.rn.f32x2 %0, %1, %2;" : "=l"(d) : "l"(a), "l"(b)); return d;
}
__device__ __forceinline__ void unpk2(ull p, float& lo, float& hi) {
    asm("mov.b64 {%0, %1}, %2;" : "=f"(lo), "=f"(hi) : "l"(p));
}

// ---------------------------------------------------------------------------
// Pack v [NV][T][B] -> g_vP[t][k2][bp]  (once per replay)
// ---------------------------------------------------------------------------
__global__ void __launch_bounds__(256) pack_v_kernel(const float* __restrict__ v)
{
    int g  = blockIdx.x * 256 + threadIdx.x;     // 0 .. 64*2048*16-1
    int bp = g & 15;
    int k2 = (g >> 4) & 2047;
    int t  = g >> 15;
    const float* base = v + (size_t)(2 * k2) * (TT * BB) + t * BB + 2 * bp;
    float2 a = *reinterpret_cast<const float2*>(base);
    float2 c = *reinterpret_cast<const float2*>(base + TT * BB);
    g_vP[g] = make_float4(a.x, a.y, c.x, c.y);
}

// ---------------------------------------------------------------------------
// Hidden kernel (f32x2): thread = (h, b-pair); strict ascending-k chain.
// 512 warps: warp = 2 h x 16 bp. grid 128, block 128.
// phase 0: t=0 hid1 (bias=b_init; cache; write rt, rP, hP)
// phase 1: t>0 hid1 (bias=seq(U@r)+b_h; cache; write rt, rP, hP)
// phase 2: hid2     (bias=cached; write r_model sample, hP)
// ---------------------------------------------------------------------------
__global__ void __launch_bounds__(128) hid2x_kernel(
    const float* __restrict__ W,
    const float* __restrict__ U,
    const float4* __restrict__ vsrc,   // packed [k2][bp]
    const float* __restrict__ bvec,
    int phase,
    float* __restrict__ r_out,   // rt column      (phase 0/1)
    float* __restrict__ s_out,   // r_model column (phase 2)
    uint32_t kk0, uint32_t kk1)
{
    const int warp = blockIdx.x * 4 + (threadIdx.x >> 5);   // 0..511
    const int lane = threadIdx.x & 31;
    const int bp   = lane & 15;
    const int h    = warp * 2 + (lane >> 4);                // 0..1023
    const int b0   = bp * 2;
    const int hb   = h * BB + b0;

    ull bias2;
    if (phase == 1) {
        ull acc = 0ull;
        const float4* Up = reinterpret_cast<const float4*>(U + (size_t)h * NHID);
        const ulonglong2* rp = reinterpret_cast<const ulonglong2*>(g_rP) + bp;
#pragma unroll 4
        for (int k4 = 0; k4 < NHID / 4; k4++) {
            float4 u4 = Up[k4];
            ulonglong2 pA = rp[(size_t)(2 * k4) * 16];
            ulonglong2 pB = rp[(size_t)(2 * k4 + 1) * 16];
            acc = ffma2(dup2(u4.x), pA.x, acc);
            acc = ffma2(dup2(u4.y), pA.y, acc);
            acc = ffma2(dup2(u4.z), pB.x, acc);
            acc = ffma2(dup2(u4.w), pB.y, acc);
        }
        bias2 = fadd2(acc, dup2(bvec[h]));
        *reinterpret_cast<ull*>(&g_bias[hb]) = bias2;
    } else if (phase == 0) {
        bias2 = dup2(bvec[h]);
        *reinterpret_cast<ull*>(&g_bias[hb]) = bias2;
    } else {
        bias2 = *reinterpret_cast<const ull*>(&g_bias[hb]);
    }

    ull acc = 0ull;
    const float4* Wp = reinterpret_cast<const float4*>(W + (size_t)h * NVIS);
    const ulonglong2* vp = reinterpret_cast<const ulonglong2*>(vsrc) + bp;
#pragma unroll 4
    for (int k4 = 0; k4 < NVIS / 4; k4++) {
        float4 w4 = Wp[k4];
        ulonglong2 pA = vp[(size_t)(2 * k4) * 16];
        ulonglong2 pB = vp[(size_t)(2 * k4 + 1) * 16];
        acc = ffma2(dup2(w4.x), pA.x, acc);
        acc = ffma2(dup2(w4.y), pA.y, acc);
        acc = ffma2(dup2(w4.z), pB.x, acc);
        acc = ffma2(dup2(w4.w), pB.y, acc);
    }
    ull logit2 = fadd2(acc, bias2);
    float l0, l1; unpk2(logit2, l0, l1);
    float r0 = sigmoidf_(l0);
    float r1 = sigmoidf_(l1);

    if (phase != 2) {
        *reinterpret_cast<float2*>(r_out + (size_t)h * (TT * BB) + b0) = make_float2(r0, r1);
        float* rpw = reinterpret_cast<float*>(&g_rP[(h >> 1) * 16 + bp]) + (h & 1) * 2;
        *reinterpret_cast<float2*>(rpw) = make_float2(r0, r1);
    }
    float u0 = jax_uniform(kk0, kk1, (uint32_t)hb);
    float u1 = jax_uniform(kk0, kk1, (uint32_t)(hb + 1));
    float s0 = (u0 < r0) ? 1.0f : 0.0f;
    float s1 = (u1 < r1) ? 1.0f : 0.0f;
    *reinterpret_cast<float2*>(&g_hP[hb]) = make_float2(s0, s1);
    if (phase == 2)
        *reinterpret_cast<float2*>(s_out + (size_t)h * (TT * BB) + b0) = make_float2(s0, s1);
}

// ---------------------------------------------------------------------------
// Visible kernel (f32x2): thread = (4 i, b-pair); strict ascending-j chains.
// 512 warps: warp = 8 i-quads x 4 bp. grid 128, block 128.
// mode 0: write vm packed -> g_vmP ; mode 1: write v_model column -> outp
// ---------------------------------------------------------------------------
__global__ void __launch_bounds__(128) vis2x_kernel(
    const float* __restrict__ W,
    const float* __restrict__ bv,
    int mode,
    float* __restrict__ outp,
    uint32_t kk0, uint32_t kk1)
{
    const int warp = blockIdx.x * 4 + (threadIdx.x >> 5);   // 0..511
    const int lane = threadIdx.x & 31;
    const int iq   = (warp & 127) * 8 + (lane & 7);         // 0..1023
    const int bp   = (warp >> 7) * 4 + (lane >> 3);         // 0..15
    const int i0   = iq * 4;
    const int b0   = bp * 2;

    ull a0 = 0ull, a1 = 0ull, a2 = 0ull, a3 = 0ull;
    const float* Wp = W + i0;
    const float* hp = g_hP + b0;

#pragma unroll 4
    for (int j = 0; j < NHID; j++) {
        float4 w4 = *reinterpret_cast<const float4*>(Wp + (size_t)j * NVIS);
        ull h2 = *reinterpret_cast<const ull*>(hp + j * BB);
        a0 = ffma2(dup2(w4.x), h2, a0);
        a1 = ffma2(dup2(w4.y), h2, a1);
        a2 = ffma2(dup2(w4.z), h2, a2);
        a3 = ffma2(dup2(w4.w), h2, a3);
    }

    ull accs[4] = {a0, a1, a2, a3};
    float s[4][2];
#pragma unroll
    for (int q = 0; q < 4; q++) {
        ull lg = fadd2(accs[q], dup2(bv[i0 + q]));
        float l0, l1; unpk2(lg, l0, l1);
        float r0 = sigmoidf_(l0);
        float r1 = sigmoidf_(l1);
        float u0 = jax_uniform(kk0, kk1, (uint32_t)((i0 + q) * BB + b0));
        float u1 = jax_uniform(kk0, kk1, (uint32_t)((i0 + q) * BB + b0 + 1));
        s[q][0] = (u0 < r0) ? 1.0f : 0.0f;
        s[q][1] = (u1 < r1) ? 1.0f : 0.0f;
    }

    if (mode == 0) {
        g_vmP[(size_t)(2 * iq) * 16 + bp]     = make_float4(s[0][0], s[0][1], s[1][0], s[1][1]);
        g_vmP[(size_t)(2 * iq + 1) * 16 + bp] = make_float4(s[2][0], s[2][1], s[3][0], s[3][1]);
    } else {
#pragma unroll
        for (int q = 0; q < 4; q++)
            *reinterpret_cast<float2*>(outp + (size_t)(i0 + q) * (TT * BB) + b0) =
                make_float2(s[q][0], s[q][1]);
    }
}

// ---------------------------------------------------------------------------
// Host: partitionable-threefry key schedule + launch sequence
// ---------------------------------------------------------------------------
extern "C" void kernel_launch(void* const* d_in, const int* in_sizes, int n_in,
                              void* d_out, int out_size)
{
    const float* v      = (const float*)d_in[0];   // [NV, T, B]
    const float* W      = (const float*)d_in[1];   // [NH, NV]
    const float* U      = (const float*)d_in[2];   // [NH, NH]
    const float* b_v    = (const float*)d_in[3];
    const float* b_h    = (const float*)d_in[4];
    const float* b_init = (const float*)d_in[5];
    float* out = (float*)d_out;

    // master key(42) = (0, 42); partitionable split: key_i = tf(key, 0, i)
    uint32_t k0a, k0b, ksa, ksb;
    tf2x32(0u, 42u, 0u, 0u, k0a, k0b);   // k0 (t=0 step key)
    tf2x32(0u, 42u, 0u, 1u, ksa, ksb);   // ks
    static uint32_t sub[TT][4][2];
    for (int t = 0; t < TT; t++) {
        uint32_t sk0, sk1;
        if (t == 0) { sk0 = k0a; sk1 = k0b; }
        else         tf2x32(ksa, ksb, 0u, (uint32_t)(t - 1), sk0, sk1);
        for (int i = 0; i < 4; i++)
            tf2x32(sk0, sk1, 0u, (uint32_t)i, sub[t][i][0], sub[t][i][1]);
    }

    void* p;
    cudaGetSymbolAddress(&p, g_vP);  const float4* pvP  = (const float4*)p;
    cudaGetSymbolAddress(&p, g_vmP); const float4* pvmP = (const float4*)p;

    pack_v_kernel<<<8192, 256>>>(v);

    for (int t = 0; t < TT; t++) {
        int ph1 = (t == 0) ? 0 : 1;
        // hid1: bias = (t==0 ? b_init : U@r + b_h); logit = W@v_t + bias
        hid2x_kernel<<<128, 128>>>(W, U, pvP + (size_t)t * 2048 * 16,
                                   (t == 0) ? b_init : b_h, ph1,
                                   out + RT_OFF + (size_t)t * BB, nullptr,
                                   sub[t][0][0], sub[t][0][1]);
        // vis1: vm = bern(sigmoid(W.T h + b_v)) -> g_vmP (packed)
        vis2x_kernel<<<128, 128>>>(W, b_v, 0, nullptr,
                                   sub[t][1][0], sub[t][1][1]);
        // hid2: logit = W@vm + cached bias -> r_model sample
        hid2x_kernel<<<128, 128>>>(W, nullptr, pvmP, nullptr, 2,
                                   nullptr, out + RM_OFF + (size_t)t * BB,
                                   sub[t][2][0], sub[t][2][1]);
        // vis2: v_model = bern(sigmoid(W.T h + b_v)) -> output column
        vis2x_kernel<<<128, 128>>>(W, b_v, 1, out + (size_t)t * BB,
                                   sub[t][3][0], sub[t][3][1]);
    }
}

// round 5
// speedup vs baseline: 3.3857x; 2.6683x over previous
#include <cuda_runtime.h>
#include <stdint.h>

#define NVIS 4096
#define NHID 1024
#define TT   64
#define BB   32

#define RM_OFF (NVIS*TT*BB)              /* 8388608  */
#define RT_OFF (RM_OFF + NHID*TT*BB)     /* 10485760 */

typedef unsigned long long ull;

// ---------------------------------------------------------------------------
// Scratch (static device globals — no allocation)
// Row layouts: X[k][b], rows of 32 floats (b contiguous)
// ---------------------------------------------------------------------------
__device__ __align__(16) float g_vT [TT * NVIS * BB];  // packed v, all t (33.5MB)
__device__ __align__(16) float g_vmT[NVIS * BB];       // vm   [k][b]
__device__ __align__(16) float g_rT [NHID * BB];       // r    [k][b]
__device__ __align__(16) float g_hP [NHID * BB];       // h    [j][b]
__device__ __align__(16) float g_bias[NHID * BB];      // bias [h][b]

// ---------------------------------------------------------------------------
// Threefry-2x32 (exact; 20 rounds, 5 key injections) — DO NOT MODIFY (passing)
// ---------------------------------------------------------------------------
__host__ __device__ __forceinline__ void tf2x32(uint32_t k0, uint32_t k1,
                                                uint32_t x0, uint32_t x1,
                                                uint32_t& o0, uint32_t& o1) {
    uint32_t ks2 = k0 ^ k1 ^ 0x1BD11BDAu;
    x0 += k0; x1 += k1;
#define TF_R(r) { x0 += x1; x1 = (x1 << (r)) | (x1 >> (32 - (r))); x1 ^= x0; }
    TF_R(13) TF_R(15) TF_R(26) TF_R(6)   x0 += k1;  x1 += ks2 + 1u;
    TF_R(17) TF_R(29) TF_R(16) TF_R(24)  x0 += ks2; x1 += k0  + 2u;
    TF_R(13) TF_R(15) TF_R(26) TF_R(6)   x0 += k0;  x1 += k1  + 3u;
    TF_R(17) TF_R(29) TF_R(16) TF_R(24)  x0 += k1;  x1 += ks2 + 4u;
    TF_R(13) TF_R(15) TF_R(26) TF_R(6)   x0 += ks2; x1 += k0  + 5u;
#undef TF_R
    o0 = x0; o1 = x1;
}

__device__ __forceinline__ float jax_uniform(uint32_t k0, uint32_t k1, uint32_t idx) {
    uint32_t o0, o1;
    tf2x32(k0, k1, 0u, idx, o0, o1);
    uint32_t bits = o0 ^ o1;
    return __uint_as_float((bits >> 9) | 0x3f800000u) - 1.0f;
}

__device__ __forceinline__ float sigmoidf_(float x) {
    return 1.0f / (1.0f + expf(-x));
}

// f32x2 helpers (per-lane IEEE identical to scalar fmaf sequence)
__device__ __forceinline__ ull dup2(float x) {
    ull r; asm("mov.b64 %0, {%1, %1};" : "=l"(r) : "f"(x)); return r;
}
__device__ __forceinline__ ull ffma2(ull a, ull b, ull c) {
    ull d; asm("fma.rn.f32x2 %0, %1, %2, %3;" : "=l"(d) : "l"(a), "l"(b), "l"(c));
    return d;
}
__device__ __forceinline__ ull fadd2(ull a, ull b) {
    ull d; asm("add.rn.f32x2 %0, %1, %2;" : "=l"(d) : "l"(a), "l"(b)); return d;
}
__device__ __forceinline__ void unpk2(ull p, float& lo, float& hi) {
    asm("mov.b64 {%0, %1}, %2;" : "=f"(lo), "=f"(hi) : "l"(p));
}

// ---------------------------------------------------------------------------
// Pack v [NV][T][B] -> g_vT[t][k][b]  (once per replay, coalesced both sides)
// ---------------------------------------------------------------------------
__global__ void __launch_bounds__(256) pack_v_kernel(const float* __restrict__ v)
{
    int g = blockIdx.x * 256 + threadIdx.x;     // 0 .. 64*4096*32-1
    int b = g & 31;
    int k = (g >> 5) & 4095;
    int t = g >> 17;
    g_vT[g] = v[(size_t)k * (TT * BB) + t * BB + b];
}

// ---------------------------------------------------------------------------
// Dot-chain with explicit double-buffered pipeline (groups of 16 k).
// Strict ascending-k order per output — bit-identical to the passing kernel.
// Mrow: row of M (float4-aligned). xsrc: [k][32] rows; thread reads pair at b0.
// ---------------------------------------------------------------------------
__device__ __forceinline__ ull chain_dot(const float4* __restrict__ Mrow4,
                                         const float* __restrict__ xsrc,
                                         int b0, int ngroups)
{
    ull acc = 0ull;
    float4 wc[4], wn[4];
    ull    vc[16], vn[16];
#pragma unroll
    for (int q = 0; q < 4; q++)  wc[q] = Mrow4[q];
#pragma unroll
    for (int q = 0; q < 16; q++) vc[q] = *(const ull*)(xsrc + (size_t)q * 32 + b0);

    for (int g = 0; g < ngroups; g++) {
        int gn = (g + 1 < ngroups) ? g + 1 : g;   // last group: redundant reload
        const float* xn = xsrc + (size_t)gn * 16 * 32 + b0;
#pragma unroll
        for (int q = 0; q < 4; q++)  wn[q] = Mrow4[gn * 4 + q];
#pragma unroll
        for (int q = 0; q < 16; q++) vn[q] = *(const ull*)(xn + (size_t)q * 32);
#pragma unroll
        for (int q = 0; q < 4; q++) {
            acc = ffma2(dup2(wc[q].x), vc[4 * q + 0], acc);
            acc = ffma2(dup2(wc[q].y), vc[4 * q + 1], acc);
            acc = ffma2(dup2(wc[q].z), vc[4 * q + 2], acc);
            acc = ffma2(dup2(wc[q].w), vc[4 * q + 3], acc);
        }
#pragma unroll
        for (int q = 0; q < 4; q++)  wc[q] = wn[q];
#pragma unroll
        for (int q = 0; q < 16; q++) vc[q] = vn[q];
    }
    return acc;
}

// ---------------------------------------------------------------------------
// Hidden kernel: thread = (1 h, b-pair). 512 warps = 128 blocks x 4 warps.
// Warp = 2 h x 16 bp -> one 128B v wavefront per k serves both h rows.
// phase 0: t=0 hid1 (bias=b_init; cache; write rt, rT, hP)
// phase 1: t>0 hid1 (bias=chain(U@r)+b_h; cache; write rt, rT, hP)
// phase 2: hid2     (bias=cached; write r_model sample, hP)
// ---------------------------------------------------------------------------
__global__ void __launch_bounds__(128, 1) hid_kernel(
    const float* __restrict__ W,
    const float* __restrict__ U,
    const float* __restrict__ vsrc,    // [k][32] rows
    const float* __restrict__ bvec,
    int phase,
    float* __restrict__ r_out,   // rt column      (phase 0/1)
    float* __restrict__ s_out,   // r_model column (phase 2)
    uint32_t kk0, uint32_t kk1)
{
    const int warp = blockIdx.x * 4 + (threadIdx.x >> 5);   // 0..511
    const int lane = threadIdx.x & 31;
    const int hs   = lane >> 4;          // 0..1
    const int bp   = lane & 15;          // 0..15
    const int h    = warp * 2 + hs;      // 0..1023
    const int b0   = bp * 2;
    const int hb   = h * BB + b0;

    ull bias2;
    if (phase == 1) {
        ull accU = chain_dot(reinterpret_cast<const float4*>(U + (size_t)h * NHID),
                             g_rT, b0, NHID / 16);
        bias2 = fadd2(accU, dup2(bvec[h]));
        *reinterpret_cast<ull*>(&g_bias[hb]) = bias2;
    } else if (phase == 0) {
        bias2 = dup2(bvec[h]);
        *reinterpret_cast<ull*>(&g_bias[hb]) = bias2;
    } else {
        bias2 = *reinterpret_cast<const ull*>(&g_bias[hb]);
    }

    ull acc = chain_dot(reinterpret_cast<const float4*>(W + (size_t)h * NVIS),
                        vsrc, b0, NVIS / 16);
    ull logit2 = fadd2(acc, bias2);
    float l0, l1; unpk2(logit2, l0, l1);
    float r0 = sigmoidf_(l0);
    float r1 = sigmoidf_(l1);

    if (phase != 2) {
        *reinterpret_cast<float2*>(r_out + (size_t)h * (TT * BB) + b0) = make_float2(r0, r1);
        *reinterpret_cast<float2*>(&g_rT[hb]) = make_float2(r0, r1);
    }
    float u0 = jax_uniform(kk0, kk1, (uint32_t)hb);
    float u1 = jax_uniform(kk0, kk1, (uint32_t)(hb + 1));
    float s0 = (u0 < r0) ? 1.0f : 0.0f;
    float s1 = (u1 < r1) ? 1.0f : 0.0f;
    *reinterpret_cast<float2*>(&g_hP[hb]) = make_float2(s0, s1);
    if (phase == 2)
        *reinterpret_cast<float2*>(s_out + (size_t)h * (TT * BB) + b0) = make_float2(s0, s1);
}

// ---------------------------------------------------------------------------
// Visible kernel: thread = (4 i, b-pair). 512 warps = 128 blocks x 4 warps.
// Warp = 8 contiguous i-quads x 4 bp -> W loads are 128B coalesced wavefronts.
// Block owns i-slice [32*blk, 32*blk+32) x all b -> no W duplication in L2.
// Strict ascending-j chain per output. Double-buffered groups of 4 j.
// mode 0: write vm -> g_vmT ; mode 1: write v_model column -> outp
// ---------------------------------------------------------------------------
__global__ void __launch_bounds__(128, 1) vis_kernel(
    const float* __restrict__ W,
    const float* __restrict__ bv,
    int mode,
    float* __restrict__ outp,
    uint32_t kk0, uint32_t kk1)
{
    const int wIn  = threadIdx.x >> 5;             // 0..3
    const int lane = threadIdx.x & 31;
    const int bp   = wIn * 4 + (lane >> 3);        // 0..15
    const int iq   = blockIdx.x * 8 + (lane & 7);  // 0..1023
    const int i0   = iq * 4;
    const int b0   = bp * 2;

    ull a0 = 0ull, a1 = 0ull, a2 = 0ull, a3 = 0ull;
    const float4* Wp = reinterpret_cast<const float4*>(W) + iq;  // W[j][i0..i0+3]
    const float*  hp = g_hP + b0;

    float4 wc[4], wn[4];
    ull    hc[4], hn[4];
#pragma unroll
    for (int q = 0; q < 4; q++) {
        wc[q] = Wp[(size_t)q * (NVIS / 4)];
        hc[q] = *(const ull*)(hp + q * 32);
    }
    for (int g = 0; g < NHID / 4; g++) {
        int gn = (g + 1 < NHID / 4) ? g + 1 : g;
#pragma unroll
        for (int q = 0; q < 4; q++) {
            wn[q] = Wp[(size_t)(gn * 4 + q) * (NVIS / 4)];
            hn[q] = *(const ull*)(hp + (gn * 4 + q) * 32);
        }
#pragma unroll
        for (int q = 0; q < 4; q++) {
            a0 = ffma2(dup2(wc[q].x), hc[q], a0);
            a1 = ffma2(dup2(wc[q].y), hc[q], a1);
            a2 = ffma2(dup2(wc[q].z), hc[q], a2);
            a3 = ffma2(dup2(wc[q].w), hc[q], a3);
        }
#pragma unroll
        for (int q = 0; q < 4; q++) { wc[q] = wn[q]; hc[q] = hn[q]; }
    }

    ull accs[4] = {a0, a1, a2, a3};
#pragma unroll
    for (int q = 0; q < 4; q++) {
        ull lg = fadd2(accs[q], dup2(bv[i0 + q]));
        float l0, l1; unpk2(lg, l0, l1);
        float r0 = sigmoidf_(l0);
        float r1 = sigmoidf_(l1);
        float u0 = jax_uniform(kk0, kk1, (uint32_t)((i0 + q) * BB + b0));
        float u1 = jax_uniform(kk0, kk1, (uint32_t)((i0 + q) * BB + b0 + 1));
        float s0 = (u0 < r0) ? 1.0f : 0.0f;
        float s1 = (u1 < r1) ? 1.0f : 0.0f;
        if (mode == 0)
            *reinterpret_cast<float2*>(&g_vmT[(size_t)(i0 + q) * BB + b0]) = make_float2(s0, s1);
        else
            *reinterpret_cast<float2*>(outp + (size_t)(i0 + q) * (TT * BB) + b0) = make_float2(s0, s1);
    }
}

// ---------------------------------------------------------------------------
// Host: partitionable-threefry key schedule + launch sequence
// ---------------------------------------------------------------------------
extern "C" void kernel_launch(void* const* d_in, const int* in_sizes, int n_in,
                              void* d_out, int out_size)
{
    const float* v      = (const float*)d_in[0];   // [NV, T, B]
    const float* W      = (const float*)d_in[1];   // [NH, NV]
    const float* U      = (const float*)d_in[2];   // [NH, NH]
    const float* b_v    = (const float*)d_in[3];
    const float* b_h    = (const float*)d_in[4];
    const float* b_init = (const float*)d_in[5];
    float* out = (float*)d_out;

    // master key(42) = (0, 42); partitionable split: key_i = tf(key, 0, i)
    uint32_t k0a, k0b, ksa, ksb;
    tf2x32(0u, 42u, 0u, 0u, k0a, k0b);   // k0 (t=0 step key)
    tf2x32(0u, 42u, 0u, 1u, ksa, ksb);   // ks
    static uint32_t sub[TT][4][2];
    for (int t = 0; t < TT; t++) {
        uint32_t sk0, sk1;
        if (t == 0) { sk0 = k0a; sk1 = k0b; }
        else         tf2x32(ksa, ksb, 0u, (uint32_t)(t - 1), sk0, sk1);
        for (int i = 0; i < 4; i++)
            tf2x32(sk0, sk1, 0u, (uint32_t)i, sub[t][i][0], sub[t][i][1]);
    }

    void* p;
    cudaGetSymbolAddress(&p, g_vT);  const float* pvT  = (const float*)p;
    cudaGetSymbolAddress(&p, g_vmT); const float* pvmT = (const float*)p;

    pack_v_kernel<<<TT * NVIS * BB / 256, 256>>>(v);

    for (int t = 0; t < TT; t++) {
        int ph1 = (t == 0) ? 0 : 1;
        // hid1: bias = (t==0 ? b_init : U@r + b_h); logit = W@v_t + bias
        hid_kernel<<<128, 128>>>(W, U, pvT + (size_t)t * NVIS * BB,
                                 (t == 0) ? b_init : b_h, ph1,
                                 out + RT_OFF + (size_t)t * BB, nullptr,
                                 sub[t][0][0], sub[t][0][1]);
        // vis1: vm = bern(sigmoid(W.T h + b_v)) -> g_vmT
        vis_kernel<<<128, 128>>>(W, b_v, 0, nullptr,
                                 sub[t][1][0], sub[t][1][1]);
        // hid2: logit = W@vm + cached bias -> r_model sample
        hid_kernel<<<128, 128>>>(W, nullptr, pvmT, nullptr, 2,
                                 nullptr, out + RM_OFF + (size_t)t * BB,
                                 sub[t][2][0], sub[t][2][1]);
        // vis2: v_model = bern(sigmoid(W.T h + b_v)) -> output column
        vis_kernel<<<128, 128>>>(W, b_v, 1, out + (size_t)t * BB,
                                 sub[t][3][0], sub[t][3][1]);
    }
}

// round 7
// speedup vs baseline: 4.7983x; 1.4172x over previous
#include <cuda_runtime.h>
#include <stdint.h>

#define NVIS 4096
#define NHID 1024
#define TT   64
#define BB   32

#define RM_OFF (NVIS*TT*BB)              /* 8388608  */
#define RT_OFF (RM_OFF + NHID*TT*BB)     /* 10485760 */

// ---------------------------------------------------------------------------
// Scratch (static device globals — no allocation)
// ---------------------------------------------------------------------------
__device__ __align__(16) uint32_t g_vbits[TT * NVIS];   // v bitmasks: word[t*NV+k], bit b
__device__ __align__(16) uint32_t g_vmbits[NVIS];       // vm bitmasks
__device__ __align__(16) uint32_t g_hbits[NHID];        // h bitmasks
__device__ __align__(16) float    g_rT[NHID * BB];      // r recurrence [h][b]
__device__ __align__(16) float    g_bias[NHID * BB];    // cached hid bias [h][b]

// ---------------------------------------------------------------------------
// Threefry-2x32 (exact; 20 rounds, 5 key injections) — DO NOT MODIFY (passing)
// ---------------------------------------------------------------------------
__host__ __device__ __forceinline__ void tf2x32(uint32_t k0, uint32_t k1,
                                                uint32_t x0, uint32_t x1,
                                                uint32_t& o0, uint32_t& o1) {
    uint32_t ks2 = k0 ^ k1 ^ 0x1BD11BDAu;
    x0 += k0; x1 += k1;
#define TF_R(r) { x0 += x1; x1 = (x1 << (r)) | (x1 >> (32 - (r))); x1 ^= x0; }
    TF_R(13) TF_R(15) TF_R(26) TF_R(6)   x0 += k1;  x1 += ks2 + 1u;
    TF_R(17) TF_R(29) TF_R(16) TF_R(24)  x0 += ks2; x1 += k0  + 2u;
    TF_R(13) TF_R(15) TF_R(26) TF_R(6)   x0 += k0;  x1 += k1  + 3u;
    TF_R(17) TF_R(29) TF_R(16) TF_R(24)  x0 += k1;  x1 += ks2 + 4u;
    TF_R(13) TF_R(15) TF_R(26) TF_R(6)   x0 += ks2; x1 += k0  + 5u;
#undef TF_R
    o0 = x0; o1 = x1;
}

__device__ __forceinline__ float jax_uniform(uint32_t k0, uint32_t k1, uint32_t idx) {
    uint32_t o0, o1;
    tf2x32(k0, k1, 0u, idx, o0, o1);
    uint32_t bits = o0 ^ o1;
    return __uint_as_float((bits >> 9) | 0x3f800000u) - 1.0f;
}

__device__ __forceinline__ float sigmoidf_(float x) {
    return 1.0f / (1.0f + expf(-x));
}

// ---------------------------------------------------------------------------
// Masked adds: acc += w if bit set. Bit-identical to fmaf(w, v, acc), v in {0,1}.
// ---------------------------------------------------------------------------
__device__ __forceinline__ void madd2(float& a0, float& a1, float w0, float w1,
                                      uint32_t word, uint32_t bb) {
    asm("{\n\t.reg .pred p;\n\t.reg .b32 t;\n\t"
        "and.b32 t, %4, %5;\n\t"
        "setp.ne.u32 p, t, 0;\n\t"
        "@p add.f32 %0, %0, %2;\n\t"
        "@p add.f32 %1, %1, %3;\n\t}"
        : "+f"(a0), "+f"(a1) : "f"(w0), "f"(w1), "r"(word), "r"(bb));
}
__device__ __forceinline__ void madd4(float& a0, float& a1, float& a2, float& a3,
                                      float4 w, uint32_t word, uint32_t bb) {
    asm("{\n\t.reg .pred p;\n\t.reg .b32 t;\n\t"
        "and.b32 t, %8, %9;\n\t"
        "setp.ne.u32 p, t, 0;\n\t"
        "@p add.f32 %0, %0, %4;\n\t"
        "@p add.f32 %1, %1, %5;\n\t"
        "@p add.f32 %2, %2, %6;\n\t"
        "@p add.f32 %3, %3, %7;\n\t}"
        : "+f"(a0), "+f"(a1), "+f"(a2), "+f"(a3)
        : "f"(w.x), "f"(w.y), "f"(w.z), "f"(w.w), "r"(word), "r"(bb));
}

// ---------------------------------------------------------------------------
// cp.async helpers
// ---------------------------------------------------------------------------
__device__ __forceinline__ uint32_t smem_u32(const void* p) {
    return (uint32_t)__cvta_generic_to_shared(p);
}
__device__ __forceinline__ void cp_async16(uint32_t saddr, const void* g) {
    asm volatile("cp.async.ca.shared.global [%0], [%1], 16;\n" :: "r"(saddr), "l"(g));
}
__device__ __forceinline__ void cp_commit() {
    asm volatile("cp.async.commit_group;\n");
}
__device__ __forceinline__ void cp_wait1() {
    asm volatile("cp.async.wait_group 1;\n" ::: "memory");
}
__device__ __forceinline__ void cp_wait0() {
    asm volatile("cp.async.wait_group 0;\n" ::: "memory");
}

// Stage one [8 rows x 512 cols] float tile (16KB) into smem. 128 threads.
__device__ __forceinline__ void stage8x512(uint32_t sbase, const float* gsrc,
                                           int rowstride, int tid) {
#pragma unroll
    for (int q = 0; q < 8; q++) {
        int cc  = q * 128 + tid;      // 0..1023
        int rr  = cc >> 7;            // 0..7
        int c16 = cc & 127;           // 16B chunk within row
        cp_async16(sbase + (uint32_t)(rr * 512 + c16 * 4) * 4,
                   gsrc + (size_t)rr * rowstride + c16 * 4);
    }
    cp_commit();
}

// ---------------------------------------------------------------------------
// Pack v [NV][T][B] -> bitmasks (once per replay)
// ---------------------------------------------------------------------------
__global__ void __launch_bounds__(256) pack_v_kernel(const float* __restrict__ v)
{
    int g    = blockIdx.x * 256 + threadIdx.x;
    int lane = g & 31;
    int w    = g >> 5;                 // 0 .. TT*NVIS-1
    int k    = w & (NVIS - 1);
    int t    = w >> 12;
    float val = v[(size_t)k * (TT * BB) + t * BB + lane];
    uint32_t m = __ballot_sync(0xffffffffu, val != 0.0f);
    if (lane == 0) g_vbits[t * NVIS + k] = m;
}

// ---------------------------------------------------------------------------
// Hidden kernel. Thread = (2 h, b); warp = h-pair x 32 b; block = 8 h (4 warps).
// Grid 128 x 128. W (and U) staged via cp.async tiles; v/vm as bitmasks.
// Strict ascending-k chain per output (bit-identical to passing kernel).
// phase 0: t=0 hid1; phase 1: t>0 hid1 (U@r bias); phase 2: hid2 (cached bias)
// ---------------------------------------------------------------------------
__global__ void __launch_bounds__(128) hid_kernel(
    const float* __restrict__ W,
    const float* __restrict__ U,
    const uint32_t* __restrict__ vbits,
    const float* __restrict__ bvec,
    int phase,
    float* __restrict__ r_out,   // rt column      (phase 0/1)
    float* __restrict__ s_out,   // r_model column (phase 2)
    uint32_t kk0, uint32_t kk1)
{
    __shared__ float sW[2][8 * 512];   // 32KB double-buffered tile
    const int tid   = threadIdx.x;
    const int wid   = tid >> 5;
    const int b     = tid & 31;
    const int hbase = blockIdx.x * 8;
    const int h0    = hbase + wid * 2;
    const int h1    = h0 + 1;
    const uint32_t bb = 1u << b;
    const uint32_t sm0 = smem_u32(&sW[0][0]);
    const uint32_t sm1 = smem_u32(&sW[1][0]);

    float bias0, bias1;
    if (phase == 1) {
        // ---- U @ r (continuous r, fmaf chain) ----
        float a0 = 0.f, a1 = 0.f;
        stage8x512(sm0, U + (size_t)hbase * NHID + 0,   NHID, tid);
        stage8x512(sm1, U + (size_t)hbase * NHID + 512, NHID, tid);
        for (int kt = 0; kt < 2; kt++) {
            if (kt == 0) cp_wait1(); else cp_wait0();
            __syncthreads();
            const float* w0p = &sW[kt][(wid * 2 + 0) * 512];
            const float* w1p = &sW[kt][(wid * 2 + 1) * 512];
            const float* rp  = g_rT + (size_t)(kt * 512) * 32 + b;
#pragma unroll 4
            for (int k = 0; k < 512; k += 4) {
                float4 w0 = *reinterpret_cast<const float4*>(w0p + k);
                float4 w1 = *reinterpret_cast<const float4*>(w1p + k);
                float r0 = rp[(k + 0) * 32];
                float r1 = rp[(k + 1) * 32];
                float r2 = rp[(k + 2) * 32];
                float r3 = rp[(k + 3) * 32];
                a0 = fmaf(w0.x, r0, a0); a1 = fmaf(w1.x, r0, a1);
                a0 = fmaf(w0.y, r1, a0); a1 = fmaf(w1.y, r1, a1);
                a0 = fmaf(w0.z, r2, a0); a1 = fmaf(w1.z, r2, a1);
                a0 = fmaf(w0.w, r3, a0); a1 = fmaf(w1.w, r3, a1);
            }
            __syncthreads();
        }
        bias0 = a0 + bvec[h0];
        bias1 = a1 + bvec[h1];
        g_bias[h0 * 32 + b] = bias0;
        g_bias[h1 * 32 + b] = bias1;
    } else if (phase == 0) {
        bias0 = bvec[h0];
        bias1 = bvec[h1];
        g_bias[h0 * 32 + b] = bias0;
        g_bias[h1 * 32 + b] = bias1;
    } else {
        bias0 = g_bias[h0 * 32 + b];
        bias1 = g_bias[h1 * 32 + b];
    }

    // ---- W @ v  (binary v via bitmask, predicated adds) ----
    float a0 = 0.f, a1 = 0.f;
    stage8x512(sm0, W + (size_t)hbase * NVIS + 0,   NVIS, tid);
    stage8x512(sm1, W + (size_t)hbase * NVIS + 512, NVIS, tid);
    for (int kt = 0; kt < 8; kt++) {
        if (kt < 7) cp_wait1(); else cp_wait0();
        __syncthreads();
        const float* w0p = &sW[kt & 1][(wid * 2 + 0) * 512];
        const float* w1p = &sW[kt & 1][(wid * 2 + 1) * 512];
        const uint32_t* vb = vbits + kt * 512;
#pragma unroll 4
        for (int k = 0; k < 512; k += 4) {
            uint4 vw = *reinterpret_cast<const uint4*>(vb + k);
            float4 w0 = *reinterpret_cast<const float4*>(w0p + k);
            float4 w1 = *reinterpret_cast<const float4*>(w1p + k);
            madd2(a0, a1, w0.x, w1.x, vw.x, bb);
            madd2(a0, a1, w0.y, w1.y, vw.y, bb);
            madd2(a0, a1, w0.z, w1.z, vw.z, bb);
            madd2(a0, a1, w0.w, w1.w, vw.w, bb);
        }
        __syncthreads();
        // FIX: tile kt+2 goes into the buffer just drained: parity kt&1
        if (kt + 2 < 8)
            stage8x512((kt & 1) ? sm1 : sm0,
                       W + (size_t)hbase * NVIS + (kt + 2) * 512, NVIS, tid);
    }

    float r0 = sigmoidf_(a0 + bias0);
    float r1 = sigmoidf_(a1 + bias1);

    if (phase != 2) {
        r_out[h0 * (TT * BB) + b] = r0;
        r_out[h1 * (TT * BB) + b] = r1;
        g_rT[h0 * 32 + b] = r0;
        g_rT[h1 * 32 + b] = r1;
    }
    float u0 = jax_uniform(kk0, kk1, (uint32_t)(h0 * BB + b));
    float u1 = jax_uniform(kk0, kk1, (uint32_t)(h1 * BB + b));
    int p0 = (u0 < r0), p1 = (u1 < r1);
    uint32_t m0 = __ballot_sync(0xffffffffu, p0);
    uint32_t m1 = __ballot_sync(0xffffffffu, p1);
    if (b == 0) { g_hbits[h0] = m0; g_hbits[h1] = m1; }
    if (phase == 2) {
        s_out[h0 * (TT * BB) + b] = p0 ? 1.0f : 0.0f;
        s_out[h1 * (TT * BB) + b] = p1 ? 1.0f : 0.0f;
    }
}

// ---------------------------------------------------------------------------
// Visible kernel. Thread = (4 i, b); warp = i-quad x 32 b; block = 16 i.
// Grid 256 x 128. W tiles [256 j x 16 i] via cp.async; h as bitmask.
// Strict ascending-j chain per output.
// mode 0: vm -> g_vmbits (ballot) ; mode 1: v_model floats -> outp
// ---------------------------------------------------------------------------
__global__ void __launch_bounds__(128) vis_kernel(
    const float* __restrict__ W,
    const float* __restrict__ bv,
    int mode,
    float* __restrict__ outp,
    uint32_t kk0, uint32_t kk1)
{
    __shared__ float sW[2][256 * 16];   // 32KB double-buffered
    const int tid   = threadIdx.x;
    const int wid   = tid >> 5;
    const int b     = tid & 31;
    const int ibase = blockIdx.x * 16;
    const int i0    = ibase + wid * 4;
    const uint32_t bb = 1u << b;
    const uint32_t sm0 = smem_u32(&sW[0][0]);
    const uint32_t sm1 = smem_u32(&sW[1][0]);

    // stage tile jt: rows j in [jt*256, jt*256+256), cols [ibase, ibase+16)
    auto stage = [&](uint32_t sbase, int jt) {
#pragma unroll
        for (int q = 0; q < 8; q++) {
            int cc  = q * 128 + tid;     // 0..1023
            int rr  = cc >> 2;           // 0..255
            int c16 = cc & 3;
            cp_async16(sbase + (uint32_t)(rr * 16 + c16 * 4) * 4,
                       W + (size_t)(jt * 256 + rr) * NVIS + ibase + c16 * 4);
        }
        cp_commit();
    };

    float a0 = 0.f, a1 = 0.f, a2 = 0.f, a3 = 0.f;
    stage(sm0, 0);
    stage(sm1, 1);
    for (int jt = 0; jt < 4; jt++) {
        if (jt < 3) cp_wait1(); else cp_wait0();
        __syncthreads();
        const float* wp = &sW[jt & 1][wid * 4];
        const uint32_t* hb = g_hbits + jt * 256;
#pragma unroll 4
        for (int j = 0; j < 256; j += 4) {
            uint4 hw = *reinterpret_cast<const uint4*>(hb + j);
            float4 w;
            w = *reinterpret_cast<const float4*>(wp + (j + 0) * 16);
            madd4(a0, a1, a2, a3, w, hw.x, bb);
            w = *reinterpret_cast<const float4*>(wp + (j + 1) * 16);
            madd4(a0, a1, a2, a3, w, hw.y, bb);
            w = *reinterpret_cast<const float4*>(wp + (j + 2) * 16);
            madd4(a0, a1, a2, a3, w, hw.z, bb);
            w = *reinterpret_cast<const float4*>(wp + (j + 3) * 16);
            madd4(a0, a1, a2, a3, w, hw.w, bb);
        }
        __syncthreads();
        // FIX: tile jt+2 goes into the buffer just drained: parity jt&1
        if (jt + 2 < 4) stage((jt & 1) ? sm1 : sm0, jt + 2);
    }

    float accs[4] = {a0, a1, a2, a3};
#pragma unroll
    for (int q = 0; q < 4; q++) {
        float r = sigmoidf_(accs[q] + bv[i0 + q]);
        float u = jax_uniform(kk0, kk1, (uint32_t)((i0 + q) * BB + b));
        int pr = (u < r);
        uint32_t m = __ballot_sync(0xffffffffu, pr);
        if (mode == 0) {
            if (b == 0) g_vmbits[i0 + q] = m;
        } else {
            outp[(size_t)(i0 + q) * (TT * BB) + b] = pr ? 1.0f : 0.0f;
        }
    }
}

// ---------------------------------------------------------------------------
// Host: partitionable-threefry key schedule + launch sequence
// ---------------------------------------------------------------------------
extern "C" void kernel_launch(void* const* d_in, const int* in_sizes, int n_in,
                              void* d_out, int out_size)
{
    const float* v      = (const float*)d_in[0];   // [NV, T, B]
    const float* W      = (const float*)d_in[1];   // [NH, NV]
    const float* U      = (const float*)d_in[2];   // [NH, NH]
    const float* b_v    = (const float*)d_in[3];
    const float* b_h    = (const float*)d_in[4];
    const float* b_init = (const float*)d_in[5];
    float* out = (float*)d_out;

    // master key(42) = (0, 42); partitionable split: key_i = tf(key, 0, i)
    uint32_t k0a, k0b, ksa, ksb;
    tf2x32(0u, 42u, 0u, 0u, k0a, k0b);   // k0 (t=0 step key)
    tf2x32(0u, 42u, 0u, 1u, ksa, ksb);   // ks
    static uint32_t sub[TT][4][2];
    for (int t = 0; t < TT; t++) {
        uint32_t sk0, sk1;
        if (t == 0) { sk0 = k0a; sk1 = k0b; }
        else         tf2x32(ksa, ksb, 0u, (uint32_t)(t - 1), sk0, sk1);
        for (int i = 0; i < 4; i++)
            tf2x32(sk0, sk1, 0u, (uint32_t)i, sub[t][i][0], sub[t][i][1]);
    }

    void* p;
    cudaGetSymbolAddress(&p, g_vbits);  const uint32_t* pvb  = (const uint32_t*)p;
    cudaGetSymbolAddress(&p, g_vmbits); const uint32_t* pvmb = (const uint32_t*)p;

    pack_v_kernel<<<TT * NVIS * 32 / 256, 256>>>(v);

    for (int t = 0; t < TT; t++) {
        int ph1 = (t == 0) ? 0 : 1;
        // hid1: bias = (t==0 ? b_init : U@r + b_h); logit = W@v_t + bias
        hid_kernel<<<128, 128>>>(W, U, pvb + (size_t)t * NVIS,
                                 (t == 0) ? b_init : b_h, ph1,
                                 out + RT_OFF + (size_t)t * BB, nullptr,
                                 sub[t][0][0], sub[t][0][1]);
        // vis1: vm = bern(sigmoid(W.T h + b_v)) -> vm bitmasks
        vis_kernel<<<256, 128>>>(W, b_v, 0, nullptr,
                                 sub[t][1][0], sub[t][1][1]);
        // hid2: logit = W@vm + cached bias -> r_model sample
        hid_kernel<<<128, 128>>>(W, nullptr, pvmb, nullptr, 2,
                                 nullptr, out + RM_OFF + (size_t)t * BB,
                                 sub[t][2][0], sub[t][2][1]);
        // vis2: v_model = bern(sigmoid(W.T h + b_v)) -> output column
        vis_kernel<<<256, 128>>>(W, b_v, 1, out + (size_t)t * BB,
                                 sub[t][3][0], sub[t][3][1]);
    }
}